// round 10
// baseline (speedup 1.0000x reference)
#include <cuda_runtime.h>
#include <cstdint>

#define NGROUPS 8
#define NTHREADS 128
#define TILE 128                        // samples per tile (1 per thread)
#define DEPTH 3                         // pipeline stages
#define STAGE_FLOATS (NGROUPS * TILE * 8)   // 8192 floats = 32KB per stage
#define OUT_FLOATS (TILE * 24)              // 3072 floats = 12KB out staging

// dynamic smem: DEPTH noise stages + out buffer + q0(8) + qg(448) + DEPTH mbarriers
#define SMEM_BYTES ((DEPTH * STAGE_FLOATS + OUT_FLOATS + 8 + 448) * 4 + DEPTH * 8)

__device__ __forceinline__ void mbar_wait(uint32_t mbar, unsigned int parity)
{
    unsigned int done;
    asm volatile(
        "{\n\t.reg .pred p;\n\t"
        "mbarrier.try_wait.parity.acquire.cta.shared::cta.b64 p, [%1], %2;\n\t"
        "selp.b32 %0, 1, 0, p;\n\t}"
        : "=r"(done) : "r"(mbar), "r"(parity) : "memory");
    while (!done) {
        asm volatile(
            "{\n\t.reg .pred p;\n\t"
            "mbarrier.try_wait.parity.acquire.cta.shared::cta.b64 p, [%1], %2, 0x989680;\n\t"
            "selp.b32 %0, 1, 0, p;\n\t}"
            : "=r"(done) : "r"(mbar), "r"(parity) : "memory");
    }
}

__global__ void __launch_bounds__(NTHREADS)
fd_sample_kernel(const float* __restrict__ q0,
                 const float* __restrict__ qg,
                 const float* __restrict__ noise0,
                 const float* __restrict__ noise,
                 float* __restrict__ out,
                 int n)
{
    extern __shared__ __align__(128) unsigned char dsm[];
    float* s_noise = reinterpret_cast<float*>(dsm);                 // DEPTH stages
    float* s_out   = s_noise + DEPTH * STAGE_FLOATS;                // 12KB staging
    float* s_q0    = s_out + OUT_FLOATS;                            // 8
    float* s_qg    = s_q0 + 8;                                      // 448
    unsigned long long* s_mbar =
        reinterpret_cast<unsigned long long*>(s_qg + 448);          // DEPTH

    const int t = threadIdx.x;
    const int ntiles = (n + TILE - 1) / TILE;
    const size_t gstride = (size_t)n * 8;

    if (t == 0) {
#pragma unroll
        for (int s = 0; s < DEPTH; s++) {
            uint32_t mb = (uint32_t)__cvta_generic_to_shared(&s_mbar[s]);
            asm volatile("mbarrier.init.shared.b64 [%0], %1;"
                         :: "r"(mb), "r"(1) : "memory");
        }
    }
    for (int k = t; k < 8; k += NTHREADS) s_q0[k] = q0[k];
    for (int k = t; k < (NGROUPS - 1) * 64; k += NTHREADS) s_qg[k] = qg[k];
    __syncthreads();   // mbarrier init + tables visible

    // ---- issue helper (thread 0 only): 8 bulk copies for one tile ----
    auto issue_tile = [&](int tile, int stage) {
        const int bstart = tile * TILE;
        const int nrem = min(TILE, n - bstart);
        const unsigned int gbytes = (unsigned int)nrem * 32u;
        uint32_t mb = (uint32_t)__cvta_generic_to_shared(&s_mbar[stage]);
        asm volatile("mbarrier.arrive.expect_tx.shared.b64 _, [%0], %1;"
                     :: "r"(mb), "r"(gbytes * NGROUPS) : "memory");
        float* sbase = s_noise + stage * STAGE_FLOATS;
        {
            uint32_t dst = (uint32_t)__cvta_generic_to_shared(sbase);
            const float* src = noise0 + (size_t)bstart * 8;
            asm volatile(
                "cp.async.bulk.shared::cta.global.mbarrier::complete_tx::bytes "
                "[%0], [%1], %2, [%3];"
                :: "r"(dst), "l"(src), "r"(gbytes), "r"(mb) : "memory");
        }
#pragma unroll
        for (int g = 1; g < NGROUPS; g++) {
            uint32_t dst = (uint32_t)__cvta_generic_to_shared(sbase + g * TILE * 8);
            const float* src = noise + (size_t)(g - 1) * gstride + (size_t)bstart * 8;
            asm volatile(
                "cp.async.bulk.shared::cta.global.mbarrier::complete_tx::bytes "
                "[%0], [%1], %2, [%3];"
                :: "r"(dst), "l"(src), "r"(gbytes), "r"(mb) : "memory");
        }
    };

    // ---- prologue: fill the pipeline ----
    if (t == 0) {
#pragma unroll
        for (int j = 0; j < DEPTH; j++) {
            int tile = blockIdx.x + j * gridDim.x;
            if (tile < ntiles) issue_tile(tile, j);
        }
    }

    // ---- steady state ----
    for (int j = 0; ; j++) {
        const int tile = blockIdx.x + j * gridDim.x;
        if (tile >= ntiles) break;
        const int stage = j % DEPTH;
        const unsigned int parity = (unsigned int)(j / DEPTH) & 1u;

        uint32_t mb = (uint32_t)__cvta_generic_to_shared(&s_mbar[stage]);
        mbar_wait(mb, parity);

        // Previous iteration's bulk out-store must finish reading s_out
        // before we overwrite it. (t0 waits; barrier orders everyone after.)
        if (t == 0 && j > 0) {
            asm volatile("cp.async.bulk.wait_group.read 0;" ::: "memory");
        }
        __syncthreads();

        const int bstart = tile * TILE;
        const int nrem = min(TILE, n - bstart);
        if (t < nrem) {
            const float* sbase = s_noise + stage * STAGE_FLOATS;
            unsigned int packed = 0;
            int best = 0;
#pragma unroll
            for (int g = 0; g < NGROUPS; g++) {
                // group 0 uses q0; g>=1 uses slice qg[g-1][best]
                // (previous argmax index IS the flattened conditioning index)
                const float* tbl = (g == 0) ? s_q0 : &s_qg[(g - 1) * 64 + best * 8];
                const float4* pv =
                    reinterpret_cast<const float4*>(sbase + g * TILE * 8 + t * 8);
                float4 a = pv[0];
                float4 b = pv[1];
                float v[8];
                v[0] = a.x; v[1] = a.y; v[2] = a.z; v[3] = a.w;
                v[4] = b.x; v[5] = b.y; v[6] = b.z; v[7] = b.w;

                int nb = 0;
                float nbv = v[0] + tbl[0];
#pragma unroll
                for (int jj = 1; jj < 8; jj++) {
                    float x = v[jj] + tbl[jj];
                    if (x > nbv) { nbv = x; nb = jj; }   // strict > == first-max
                }
                best = nb;
                packed = (packed << 3) | (unsigned int)best;
            }

            // stage the 24 output floats in smem (linear, matches global layout)
            float4* po = reinterpret_cast<float4*>(s_out + t * 24);
#pragma unroll
            for (int k = 0; k < 6; k++) {
                float4 w;
                w.x = (float)((packed >> (23 - (k * 4 + 0))) & 1u);
                w.y = (float)((packed >> (23 - (k * 4 + 1))) & 1u);
                w.z = (float)((packed >> (23 - (k * 4 + 2))) & 1u);
                w.w = (float)((packed >> (23 - (k * 4 + 3))) & 1u);
                po[k] = w;
            }
        }

        __syncthreads();   // stage consumed + s_out complete
        if (t == 0) {
            // order generic STS before async-proxy bulk read
            asm volatile("fence.proxy.async.shared::cta;" ::: "memory");
            // one contiguous 12KB burst store for the whole tile
            uint32_t src = (uint32_t)__cvta_generic_to_shared(s_out);
            float* dst = out + (size_t)bstart * 24;
            const unsigned int obytes = (unsigned int)nrem * 96u;
            asm volatile(
                "cp.async.bulk.global.shared::cta.bulk_group [%0], [%1], %2;"
                :: "l"(dst), "r"(src), "r"(obytes) : "memory");
            asm volatile("cp.async.bulk.commit_group;" ::: "memory");
            // refill the freed noise stage
            const int tile_next = blockIdx.x + (j + DEPTH) * gridDim.x;
            if (tile_next < ntiles) issue_tile(tile_next, stage);
        }
    }

    // drain the final out-store before exit
    if (t == 0) {
        asm volatile("cp.async.bulk.wait_group.read 0;" ::: "memory");
    }
}

extern "C" void kernel_launch(void* const* d_in, const int* in_sizes, int n_in,
                              void* d_out, int out_size)
{
    // Identify inputs by element count — robust to harness input ordering.
    //   q0: 8 | qg: 448 | noise0: N*8 | noise: (G-1)*N*8
    const float* q0 = nullptr;
    const float* qg = nullptr;
    const float* noise0 = nullptr;
    const float* noise = nullptr;
    long long n0_sz = 0;

    for (int k = 0; k < n_in; k++) {
        long long sz = in_sizes[k];
        const float* p = (const float*)d_in[k];
        if (sz == 8) {
            q0 = p;
        } else if (sz == (NGROUPS - 1) * 64) {
            qg = p;
        } else {
            if (noise0 == nullptr) { noise0 = p; n0_sz = sz; }
            else if (sz > n0_sz)   { noise = p; }
            else { noise = noise0; noise0 = p; n0_sz = sz; }
        }
    }

    const int n = (int)(n0_sz / 8);   // N samples
    const int ntiles = (n + TILE - 1) / TILE;

    cudaFuncSetAttribute(fd_sample_kernel,
                         cudaFuncAttributeMaxDynamicSharedMemorySize, SMEM_BYTES);

    int blocks = 2 * 148;              // persistent: 2 CTAs per SM
    if (blocks > ntiles) blocks = ntiles;
    fd_sample_kernel<<<blocks, NTHREADS, SMEM_BYTES>>>(q0, qg, noise0, noise,
                                                       (float*)d_out, n);
}

// round 13
// speedup vs baseline: 1.2651x; 1.2651x over previous
#include <cuda_runtime.h>
#include <cstdint>

#define NGROUPS 8
#define NTHREADS 128
#define NWARPS (NTHREADS / 32)
#define TILE 128                        // samples per tile (1 per thread)
#define DEPTH 3                         // pipeline stages
#define STAGE_FLOATS (NGROUPS * TILE * 8)   // 8192 floats = 32KB per stage

// dynamic smem: DEPTH stages + q0(8) + qg(448) + 2*DEPTH mbarriers (full+empty)
#define SMEM_BYTES (DEPTH * STAGE_FLOATS * 4 + (8 + 448) * 4 + 2 * DEPTH * 8)

__device__ __forceinline__ void mbar_wait(uint32_t mbar, unsigned int parity)
{
    unsigned int done;
    asm volatile(
        "{\n\t.reg .pred p;\n\t"
        "mbarrier.try_wait.parity.acquire.cta.shared::cta.b64 p, [%1], %2;\n\t"
        "selp.b32 %0, 1, 0, p;\n\t}"
        : "=r"(done) : "r"(mbar), "r"(parity) : "memory");
    while (!done) {
        asm volatile(
            "{\n\t.reg .pred p;\n\t"
            "mbarrier.try_wait.parity.acquire.cta.shared::cta.b64 p, [%1], %2, 0x989680;\n\t"
            "selp.b32 %0, 1, 0, p;\n\t}"
            : "=r"(done) : "r"(mbar), "r"(parity) : "memory");
    }
}

__global__ void __launch_bounds__(NTHREADS)
fd_sample_kernel(const float* __restrict__ q0,
                 const float* __restrict__ qg,
                 const float* __restrict__ noise0,
                 const float* __restrict__ noise,
                 float* __restrict__ out,
                 int n)
{
    extern __shared__ __align__(128) unsigned char dsm[];
    float* s_noise = reinterpret_cast<float*>(dsm);                 // DEPTH stages
    float* s_q0    = s_noise + DEPTH * STAGE_FLOATS;                // 8
    float* s_qg    = s_q0 + 8;                                      // 448
    unsigned long long* s_full =
        reinterpret_cast<unsigned long long*>(s_qg + 448);          // DEPTH
    unsigned long long* s_empty = s_full + DEPTH;                   // DEPTH

    const int t = threadIdx.x;
    const int lane = t & 31;
    const int ntiles = (n + TILE - 1) / TILE;
    const size_t gstride = (size_t)n * 8;

    if (t == 0) {
#pragma unroll
        for (int s = 0; s < DEPTH; s++) {
            uint32_t mf = (uint32_t)__cvta_generic_to_shared(&s_full[s]);
            uint32_t me = (uint32_t)__cvta_generic_to_shared(&s_empty[s]);
            asm volatile("mbarrier.init.shared.b64 [%0], %1;"
                         :: "r"(mf), "r"(1) : "memory");
            asm volatile("mbarrier.init.shared.b64 [%0], %1;"
                         :: "r"(me), "r"(NWARPS) : "memory");
        }
    }
    for (int k = t; k < 8; k += NTHREADS) s_q0[k] = q0[k];
    for (int k = t; k < (NGROUPS - 1) * 64; k += NTHREADS) s_qg[k] = qg[k];
    __syncthreads();   // mbarrier init + tables visible

    // ---- issue helper (thread 0 only): 8 bulk copies for one tile ----
    auto issue_tile = [&](int tile, int stage) {
        const int bstart = tile * TILE;
        const int nrem = min(TILE, n - bstart);
        const unsigned int gbytes = (unsigned int)nrem * 32u;
        uint32_t mf = (uint32_t)__cvta_generic_to_shared(&s_full[stage]);
        asm volatile("mbarrier.arrive.expect_tx.shared.b64 _, [%0], %1;"
                     :: "r"(mf), "r"(gbytes * NGROUPS) : "memory");
        float* sbase = s_noise + stage * STAGE_FLOATS;
        {
            uint32_t dst = (uint32_t)__cvta_generic_to_shared(sbase);
            const float* src = noise0 + (size_t)bstart * 8;
            asm volatile(
                "cp.async.bulk.shared::cta.global.mbarrier::complete_tx::bytes "
                "[%0], [%1], %2, [%3];"
                :: "r"(dst), "l"(src), "r"(gbytes), "r"(mf) : "memory");
        }
#pragma unroll
        for (int g = 1; g < NGROUPS; g++) {
            uint32_t dst = (uint32_t)__cvta_generic_to_shared(sbase + g * TILE * 8);
            const float* src = noise + (size_t)(g - 1) * gstride + (size_t)bstart * 8;
            asm volatile(
                "cp.async.bulk.shared::cta.global.mbarrier::complete_tx::bytes "
                "[%0], [%1], %2, [%3];"
                :: "r"(dst), "l"(src), "r"(gbytes), "r"(mf) : "memory");
        }
    };

    // ---- prologue: fill the pipeline (stages start empty) ----
    if (t == 0) {
#pragma unroll
        for (int j = 0; j < DEPTH; j++) {
            int tile = blockIdx.x + j * gridDim.x;
            if (tile < ntiles) issue_tile(tile, j);
        }
    }

    // ---- steady state: no full-block barrier per tile ----
    for (int j = 0; ; j++) {
        const int tile = blockIdx.x + j * gridDim.x;
        if (tile >= ntiles) break;
        const int stage = j % DEPTH;
        const unsigned int parity = (unsigned int)(j / DEPTH) & 1u;

        uint32_t mf = (uint32_t)__cvta_generic_to_shared(&s_full[stage]);
        uint32_t me = (uint32_t)__cvta_generic_to_shared(&s_empty[stage]);
        mbar_wait(mf, parity);

        const int bstart = tile * TILE;
        const int nrem = min(TILE, n - bstart);
        if (t < nrem) {
            const float* sbase = s_noise + stage * STAGE_FLOATS;
            unsigned int packed = 0;
            int best = 0;
#pragma unroll
            for (int g = 0; g < NGROUPS; g++) {
                // group 0 uses q0; g>=1 uses slice qg[g-1][best]
                // (previous argmax index IS the flattened conditioning index)
                const float* tbl = (g == 0) ? s_q0 : &s_qg[(g - 1) * 64 + best * 8];
                const float4* pv =
                    reinterpret_cast<const float4*>(sbase + g * TILE * 8 + t * 8);
                float4 a = pv[0];
                float4 b = pv[1];
                float v[8];
                v[0] = a.x; v[1] = a.y; v[2] = a.z; v[3] = a.w;
                v[4] = b.x; v[5] = b.y; v[6] = b.z; v[7] = b.w;

                int nb = 0;
                float nbv = v[0] + tbl[0];
#pragma unroll
                for (int jj = 1; jj < 8; jj++) {
                    float x = v[jj] + tbl[jj];
                    if (x > nbv) { nbv = x; nb = jj; }   // strict > == first-max
                }
                best = nb;
                packed = (packed << 3) | (unsigned int)best;
            }

            float4* po = reinterpret_cast<float4*>(out + (size_t)(bstart + t) * 24);
#pragma unroll
            for (int k = 0; k < 6; k++) {
                float4 w;
                w.x = (float)((packed >> (23 - (k * 4 + 0))) & 1u);
                w.y = (float)((packed >> (23 - (k * 4 + 1))) & 1u);
                w.z = (float)((packed >> (23 - (k * 4 + 2))) & 1u);
                w.w = (float)((packed >> (23 - (k * 4 + 3))) & 1u);
                __stcs(po + k, w);
            }
        }

        // this warp is done reading the stage: one arrival per warp
        __syncwarp();
        if (lane == 0) {
            asm volatile("mbarrier.arrive.shared.b64 _, [%0];"
                         :: "r"(me) : "memory");
        }

        // producer: refill this stage once ALL warps have arrived empty
        if (t == 0) {
            const int tile_next = blockIdx.x + (j + DEPTH) * gridDim.x;
            if (tile_next < ntiles) {
                mbar_wait(me, parity);   // empty phase for this occupancy round
                issue_tile(tile_next, stage);
            }
        }
    }
}

extern "C" void kernel_launch(void* const* d_in, const int* in_sizes, int n_in,
                              void* d_out, int out_size)
{
    // Identify inputs by element count — robust to harness input ordering.
    //   q0: 8 | qg: 448 | noise0: N*8 | noise: (G-1)*N*8
    const float* q0 = nullptr;
    const float* qg = nullptr;
    const float* noise0 = nullptr;
    const float* noise = nullptr;
    long long n0_sz = 0;

    for (int k = 0; k < n_in; k++) {
        long long sz = in_sizes[k];
        const float* p = (const float*)d_in[k];
        if (sz == 8) {
            q0 = p;
        } else if (sz == (NGROUPS - 1) * 64) {
            qg = p;
        } else {
            if (noise0 == nullptr) { noise0 = p; n0_sz = sz; }
            else if (sz > n0_sz)   { noise = p; }
            else { noise = noise0; noise0 = p; n0_sz = sz; }
        }
    }

    const int n = (int)(n0_sz / 8);   // N samples
    const int ntiles = (n + TILE - 1) / TILE;

    cudaFuncSetAttribute(fd_sample_kernel,
                         cudaFuncAttributeMaxDynamicSharedMemorySize, SMEM_BYTES);

    int blocks = 2 * 148;              // persistent: 2 CTAs per SM
    if (blocks > ntiles) blocks = ntiles;
    fd_sample_kernel<<<blocks, NTHREADS, SMEM_BYTES>>>(q0, qg, noise0, noise,
                                                       (float*)d_out, n);
}

// round 17
// speedup vs baseline: 1.3105x; 1.0359x over previous
#include <cuda_runtime.h>
#include <cstdint>

#define NGROUPS 8
#define NTHREADS 256
#define NWARPS (NTHREADS / 32)
#define TILE 256                        // samples per tile (1 per thread)
#define DEPTH 3                         // pipeline stages
#define STAGE_FLOATS (NGROUPS * TILE * 8)   // 16384 floats = 64KB per stage

// dynamic smem: DEPTH stages + q0(8) + qg(448) + 2*DEPTH mbarriers (full+empty)
#define SMEM_BYTES (DEPTH * STAGE_FLOATS * 4 + (8 + 448) * 4 + 2 * DEPTH * 8)

__device__ __forceinline__ void mbar_wait(uint32_t mbar, unsigned int parity)
{
    unsigned int done;
    asm volatile(
        "{\n\t.reg .pred p;\n\t"
        "mbarrier.try_wait.parity.acquire.cta.shared::cta.b64 p, [%1], %2;\n\t"
        "selp.b32 %0, 1, 0, p;\n\t}"
        : "=r"(done) : "r"(mbar), "r"(parity) : "memory");
    while (!done) {
        asm volatile(
            "{\n\t.reg .pred p;\n\t"
            "mbarrier.try_wait.parity.acquire.cta.shared::cta.b64 p, [%1], %2, 0x989680;\n\t"
            "selp.b32 %0, 1, 0, p;\n\t}"
            : "=r"(done) : "r"(mbar), "r"(parity) : "memory");
    }
}

__global__ void __launch_bounds__(NTHREADS)
fd_sample_kernel(const float* __restrict__ q0,
                 const float* __restrict__ qg,
                 const float* __restrict__ noise0,
                 const float* __restrict__ noise,
                 float* __restrict__ out,
                 int n)
{
    extern __shared__ __align__(128) unsigned char dsm[];
    float* s_noise = reinterpret_cast<float*>(dsm);                 // DEPTH stages
    float* s_q0    = s_noise + DEPTH * STAGE_FLOATS;                // 8
    float* s_qg    = s_q0 + 8;                                      // 448
    unsigned long long* s_full =
        reinterpret_cast<unsigned long long*>(s_qg + 448);          // DEPTH
    unsigned long long* s_empty = s_full + DEPTH;                   // DEPTH

    const int t = threadIdx.x;
    const int lane = t & 31;
    const int ntiles = (n + TILE - 1) / TILE;
    const size_t gstride = (size_t)n * 8;

    if (t == 0) {
#pragma unroll
        for (int s = 0; s < DEPTH; s++) {
            uint32_t mf = (uint32_t)__cvta_generic_to_shared(&s_full[s]);
            uint32_t me = (uint32_t)__cvta_generic_to_shared(&s_empty[s]);
            asm volatile("mbarrier.init.shared.b64 [%0], %1;"
                         :: "r"(mf), "r"(1) : "memory");
            asm volatile("mbarrier.init.shared.b64 [%0], %1;"
                         :: "r"(me), "r"(NWARPS) : "memory");
        }
    }
    for (int k = t; k < 8; k += NTHREADS) s_q0[k] = q0[k];
    for (int k = t; k < (NGROUPS - 1) * 64; k += NTHREADS) s_qg[k] = qg[k];
    __syncthreads();   // mbarrier init + tables visible

    // ---- issue helper (thread 0 only): 8 bulk copies for one tile ----
    auto issue_tile = [&](int tile, int stage) {
        const int bstart = tile * TILE;
        const int nrem = min(TILE, n - bstart);
        const unsigned int gbytes = (unsigned int)nrem * 32u;
        uint32_t mf = (uint32_t)__cvta_generic_to_shared(&s_full[stage]);
        asm volatile("mbarrier.arrive.expect_tx.shared.b64 _, [%0], %1;"
                     :: "r"(mf), "r"(gbytes * NGROUPS) : "memory");
        float* sbase = s_noise + stage * STAGE_FLOATS;
        {
            uint32_t dst = (uint32_t)__cvta_generic_to_shared(sbase);
            const float* src = noise0 + (size_t)bstart * 8;
            asm volatile(
                "cp.async.bulk.shared::cta.global.mbarrier::complete_tx::bytes "
                "[%0], [%1], %2, [%3];"
                :: "r"(dst), "l"(src), "r"(gbytes), "r"(mf) : "memory");
        }
#pragma unroll
        for (int g = 1; g < NGROUPS; g++) {
            uint32_t dst = (uint32_t)__cvta_generic_to_shared(sbase + g * TILE * 8);
            const float* src = noise + (size_t)(g - 1) * gstride + (size_t)bstart * 8;
            asm volatile(
                "cp.async.bulk.shared::cta.global.mbarrier::complete_tx::bytes "
                "[%0], [%1], %2, [%3];"
                :: "r"(dst), "l"(src), "r"(gbytes), "r"(mf) : "memory");
        }
    };

    // ---- prologue: fill the pipeline (stages start empty) ----
    if (t == 0) {
#pragma unroll
        for (int j = 0; j < DEPTH; j++) {
            int tile = blockIdx.x + j * gridDim.x;
            if (tile < ntiles) issue_tile(tile, j);
        }
    }

    // ---- steady state: warp-granular empty arrivals, no block barrier ----
    for (int j = 0; ; j++) {
        const int tile = blockIdx.x + j * gridDim.x;
        if (tile >= ntiles) break;
        const int stage = j % DEPTH;
        const unsigned int parity = (unsigned int)(j / DEPTH) & 1u;

        uint32_t mf = (uint32_t)__cvta_generic_to_shared(&s_full[stage]);
        uint32_t me = (uint32_t)__cvta_generic_to_shared(&s_empty[stage]);
        mbar_wait(mf, parity);

        const int bstart = tile * TILE;
        const int nrem = min(TILE, n - bstart);
        if (t < nrem) {
            const float* sbase = s_noise + stage * STAGE_FLOATS;
            unsigned int packed = 0;
            int best = 0;
#pragma unroll
            for (int g = 0; g < NGROUPS; g++) {
                // group 0 uses q0; g>=1 uses slice qg[g-1][best]
                // (previous argmax index IS the flattened conditioning index)
                const float* tbl = (g == 0) ? s_q0 : &s_qg[(g - 1) * 64 + best * 8];
                const float4* pv =
                    reinterpret_cast<const float4*>(sbase + g * TILE * 8 + t * 8);
                float4 a = pv[0];
                float4 b = pv[1];
                float v[8];
                v[0] = a.x; v[1] = a.y; v[2] = a.z; v[3] = a.w;
                v[4] = b.x; v[5] = b.y; v[6] = b.z; v[7] = b.w;

                int nb = 0;
                float nbv = v[0] + tbl[0];
#pragma unroll
                for (int jj = 1; jj < 8; jj++) {
                    float x = v[jj] + tbl[jj];
                    if (x > nbv) { nbv = x; nb = jj; }   // strict > == first-max
                }
                best = nb;
                packed = (packed << 3) | (unsigned int)best;
            }

            // default (write-back) stores: let the 126MB L2 buffer the
            // 96MB output stream instead of forcing eager writebacks
            float4* po = reinterpret_cast<float4*>(out + (size_t)(bstart + t) * 24);
#pragma unroll
            for (int k = 0; k < 6; k++) {
                float4 w;
                w.x = (float)((packed >> (23 - (k * 4 + 0))) & 1u);
                w.y = (float)((packed >> (23 - (k * 4 + 1))) & 1u);
                w.z = (float)((packed >> (23 - (k * 4 + 2))) & 1u);
                w.w = (float)((packed >> (23 - (k * 4 + 3))) & 1u);
                po[k] = w;
            }
        }

        // this warp is done reading the stage: one arrival per warp
        __syncwarp();
        if (lane == 0) {
            asm volatile("mbarrier.arrive.shared.b64 _, [%0];"
                         :: "r"(me) : "memory");
        }

        // producer: refill this stage once ALL warps have arrived empty
        if (t == 0) {
            const int tile_next = blockIdx.x + (j + DEPTH) * gridDim.x;
            if (tile_next < ntiles) {
                mbar_wait(me, parity);   // empty phase for this occupancy round
                issue_tile(tile_next, stage);
            }
        }
    }
}

extern "C" void kernel_launch(void* const* d_in, const int* in_sizes, int n_in,
                              void* d_out, int out_size)
{
    // Identify inputs by element count — robust to harness input ordering.
    //   q0: 8 | qg: 448 | noise0: N*8 | noise: (G-1)*N*8
    const float* q0 = nullptr;
    const float* qg = nullptr;
    const float* noise0 = nullptr;
    const float* noise = nullptr;
    long long n0_sz = 0;

    for (int k = 0; k < n_in; k++) {
        long long sz = in_sizes[k];
        const float* p = (const float*)d_in[k];
        if (sz == 8) {
            q0 = p;
        } else if (sz == (NGROUPS - 1) * 64) {
            qg = p;
        } else {
            if (noise0 == nullptr) { noise0 = p; n0_sz = sz; }
            else if (sz > n0_sz)   { noise = p; }
            else { noise = noise0; noise0 = p; n0_sz = sz; }
        }
    }

    const int n = (int)(n0_sz / 8);   // N samples
    const int ntiles = (n + TILE - 1) / TILE;

    cudaFuncSetAttribute(fd_sample_kernel,
                         cudaFuncAttributeMaxDynamicSharedMemorySize, SMEM_BYTES);

    int blocks = 148;                  // persistent: 1 CTA per SM (64KB stages)
    if (blocks > ntiles) blocks = ntiles;
    fd_sample_kernel<<<blocks, NTHREADS, SMEM_BYTES>>>(q0, qg, noise0, noise,
                                                       (float*)d_out, n);
}